// round 17
// baseline (speedup 1.0000x reference)
#include <cuda_runtime.h>
#include <cuda_fp16.h>

// GuidedFilter, causal box window R=20 (trailing, clamped prefix at edges), H then W.
// Stage1: box{I,p,Ip,I2} -> A,b (fp16 half2 scratch).  Stage2: box{A,b} -> q.
//
// R17 = R15 overlapped warp tiling (warp loads 128 cols / outputs 108; window ==
// shfl_up(prefix,5); fp16 scratch; __ldcs/__stcs) + ROW-PAIR main loop:
//   warm-up rows (bands>=1; accumulate only, no sub possible, no output)
//   then 32 row-pairs: loads for both rows issued together (2x MLP);
//   update(g0) -> { hwin(g0)  ||  update(g1) } -> hwin(g1): the two rows'
//   shfl/FADD chains overlap, halving exposed latency per row.
// Exactness per-row unchanged: gi<R exact sequential vertical path, exact
// division on edges, clamped prefix via zero-loaded lanes in warp 0.

#define Hn 1024
#define Wn 1024
#define NIMG 24
#define R 20
#define NBAND 16
#define BANDH 64
#define TPB 320

// AB scratch: uint4 = 4 pixels x half2(A,b). 96 MB.
__device__ uint4 g_ABh[(size_t)NIMG * Hn * (Wn / 4)];

__device__ __forceinline__ unsigned int h2u(__half2 h) {
    return *reinterpret_cast<unsigned int*>(&h);
}
__device__ __forceinline__ void upk(unsigned int u, float& a, float& b) {
    __half2 h = *reinterpret_cast<__half2*>(&u);
    float2 f = __half22float2(h);
    a = f.x; b = f.y;
}

// Width-20 window, 4 elems/lane, subtrahend 5 lanes up. Valid for lane >= 5.
__device__ __forceinline__ void hwin(const float v[4], float w[4])
{
    const float p0 = v[0];
    const float p1 = __fadd_rn(p0, v[1]);
    const float p2 = __fadd_rn(p1, v[2]);
    const float p3 = __fadd_rn(p2, v[3]);
    const float T  = p3;

    const float t1 = __shfl_up_sync(0xffffffffu, T, 1);
    const float t2 = __shfl_up_sync(0xffffffffu, T, 2);
    const float t3 = __shfl_up_sync(0xffffffffu, T, 3);
    const float t4 = __shfl_up_sync(0xffffffffu, T, 4);
    const float t5 = __shfl_up_sync(0xffffffffu, T, 5);
    const float s0 = __shfl_up_sync(0xffffffffu, p0, 5);
    const float s1 = __shfl_up_sync(0xffffffffu, p1, 5);
    const float s2 = __shfl_up_sync(0xffffffffu, p2, 5);
    const float s3 = t5;                  // p3 == T

    float sumT = 0.0f;
    sumT = __fadd_rn(sumT, t1);
    sumT = __fadd_rn(sumT, t2);
    sumT = __fadd_rn(sumT, t3);
    sumT = __fadd_rn(sumT, t4);
    sumT = __fadd_rn(sumT, t5);

    w[0] = __fsub_rn(__fadd_rn(p0, sumT), s0);
    w[1] = __fsub_rn(__fadd_rn(p1, sumT), s1);
    w[2] = __fsub_rn(__fadd_rn(p2, sumT), s2);
    w[3] = __fsub_rn(__fadd_rn(p3, sumT), s3);
}

// stage1 vertical update (exact ordering switch per row)
__device__ __forceinline__ void s1_upd(float vI[4], float vP[4], float vIP[4], float vII[4],
                                       const float4 In, const float4 Pn,
                                       const float4 Io, const float4 Po, bool exact)
{
    const float in_[4] = {In.x, In.y, In.z, In.w};
    const float pn_[4] = {Pn.x, Pn.y, Pn.z, Pn.w};
    const float io_[4] = {Io.x, Io.y, Io.z, Io.w};
    const float po_[4] = {Po.x, Po.y, Po.z, Po.w};
    if (exact) {
#pragma unroll
        for (int e = 0; e < 4; ++e) {
            vI[e]  = __fsub_rn(__fadd_rn(vI[e],  in_[e]), io_[e]);
            vP[e]  = __fsub_rn(__fadd_rn(vP[e],  pn_[e]), po_[e]);
            vIP[e] = __fsub_rn(__fadd_rn(vIP[e], __fmul_rn(in_[e], pn_[e])),
                               __fmul_rn(io_[e], po_[e]));
            vII[e] = __fsub_rn(__fadd_rn(vII[e], __fmul_rn(in_[e], in_[e])),
                               __fmul_rn(io_[e], io_[e]));
        }
    } else {
#pragma unroll
        for (int e = 0; e < 4; ++e) {
            vI[e]  = __fsub_rn(__fadd_rn(vI[e],  in_[e]), io_[e]);
            vP[e]  = __fsub_rn(__fadd_rn(vP[e],  pn_[e]), po_[e]);
            vIP[e] = fmaf(in_[e], pn_[e], fmaf(-io_[e], po_[e], vIP[e]));
            vII[e] = fmaf(in_[e], in_[e], fmaf(-io_[e], io_[e], vII[e]));
        }
    }
}

// stage1 epilogue for one row (hwin outputs already computed)
__device__ __forceinline__ void s1_epi(const float w0[4], const float w1[4],
                                       const float w2[4], const float w3[4],
                                       int gi, int col0, bool strip0, int lane,
                                       uint4* __restrict__ dst)
{
    const float inv400 = 1.0f / 400.0f;
    const bool divpath = (gi + 1 < R) || (strip0 && lane < 10);
    float A_[4], b_[4];
    if (divpath) {
        const float Nrf = (gi + 1 < R) ? (float)(gi + 1) : 20.0f;
#pragma unroll
        for (int e = 0; e < 4; ++e) {
            const int colp1 = col0 + e + 1;
            const float Ncf = (colp1 < R) ? (float)colp1 : 20.0f;
            const float Nf = __fmul_rn(Nrf, Ncf);
            const float m0 = __fdiv_rn(w0[e], Nf);
            const float m1 = __fdiv_rn(w1[e], Nf);
            const float m2 = __fdiv_rn(w2[e], Nf);
            const float m3 = __fdiv_rn(w3[e], Nf);
            const float cov = __fsub_rn(m2, __fmul_rn(m0, m1));
            const float var = __fsub_rn(m3, __fmul_rn(m0, m0));
            A_[e] = __fdiv_rn(cov, __fadd_rn(var, 1e-8f));
            b_[e] = __fsub_rn(m1, __fmul_rn(A_[e], m0));
        }
    } else {
#pragma unroll
        for (int e = 0; e < 4; ++e) {
            const float m0 = w0[e] * inv400;
            const float m1 = w1[e] * inv400;
            const float m2 = w2[e] * inv400;
            const float m3 = w3[e] * inv400;
            const float cov = fmaf(-m0, m1, m2);
            const float var = fmaf(-m0, m0, m3);
            const float A = __fdividef(cov, var + 1e-8f);
            A_[e] = A;
            b_[e] = fmaf(-A, m0, m1);
        }
    }
    uint4 st;
    st.x = h2u(__floats2half2_rn(A_[0], b_[0]));
    st.y = h2u(__floats2half2_rn(A_[1], b_[1]));
    st.z = h2u(__floats2half2_rn(A_[2], b_[2]));
    st.w = h2u(__floats2half2_rn(A_[3], b_[3]));
    __stcs(dst, st);
}

__global__ void __launch_bounds__(TPB, 2)
gf_stage1(const float* __restrict__ gI, const float* __restrict__ gP)
{
    const int lane = threadIdx.x & 31;
    const int j    = threadIdx.x >> 5;
    const int band = blockIdx.x;
    const int img  = blockIdx.y;

    const int mi   = 27 * j - 5 + lane;
    const bool inc = (mi >= 0) && (mi < 256);
    const bool isOut = (lane >= 5) && (mi < 256);
    const int col0 = mi * 4;
    const bool strip0 = (j == 0);

    const int r0 = band * BANDH;
    const int r1 = r0 + BANDH;
    const int gstart = (r0 >= R - 1) ? (r0 - (R - 1)) : 0;
    const int subStart = gstart + R;

    const float4* I4 = (const float4*)(gI + (size_t)img * Hn * Wn);
    const float4* P4 = (const float4*)(gP + (size_t)img * Hn * Wn);
    uint4* ABu = g_ABh + (size_t)img * Hn * (Wn / 4);

    float vI[4]  = {0,0,0,0}, vP[4]  = {0,0,0,0};
    float vIP[4] = {0,0,0,0}, vII[4] = {0,0,0,0};
    const float4 zf4 = make_float4(0.f,0.f,0.f,0.f);

    // warm-up (bands >= 1): pure accumulation, gi >= R always, gi < subStart always
    for (int gi = gstart; gi < r0; ++gi) {
        float4 In = zf4, Pn = zf4;
        if (inc) { In = I4[(gi << 8) + mi]; Pn = P4[(gi << 8) + mi]; }
        s1_upd(vI, vP, vIP, vII, In, Pn, zf4, zf4, false);
    }

    // main loop: row pairs (BANDH even)
    for (int gi = r0; gi < r1; gi += 2) {
        const int g0 = gi, g1 = gi + 1;
        float4 In0 = zf4, Pn0 = zf4, Io0 = zf4, Po0 = zf4;
        float4 In1 = zf4, Pn1 = zf4, Io1 = zf4, Po1 = zf4;
        if (inc) {
            In0 = I4[(g0 << 8) + mi]; Pn0 = P4[(g0 << 8) + mi];
            In1 = I4[(g1 << 8) + mi]; Pn1 = P4[(g1 << 8) + mi];
            if (g0 >= subStart) {
                Io0 = __ldcs(I4 + ((g0 - R) << 8) + mi);
                Po0 = __ldcs(P4 + ((g0 - R) << 8) + mi);
            }
            if (g1 >= subStart) {
                Io1 = __ldcs(I4 + ((g1 - R) << 8) + mi);
                Po1 = __ldcs(P4 + ((g1 - R) << 8) + mi);
            }
        }

        s1_upd(vI, vP, vIP, vII, In0, Pn0, Io0, Po0, g0 < R);
        float w0a[4], w1a[4], w2a[4], w3a[4];
        hwin(vI,  w0a); hwin(vP,  w1a); hwin(vIP, w2a); hwin(vII, w3a);

        s1_upd(vI, vP, vIP, vII, In1, Pn1, Io1, Po1, g1 < R);
        float w0b[4], w1b[4], w2b[4], w3b[4];
        hwin(vI,  w0b); hwin(vP,  w1b); hwin(vIP, w2b); hwin(vII, w3b);

        if (isOut) {
            s1_epi(w0a, w1a, w2a, w3a, g0, col0, strip0, lane, ABu + (g0 << 8) + mi);
            s1_epi(w0b, w1b, w2b, w3b, g1, col0, strip0, lane, ABu + (g1 << 8) + mi);
        }
    }
}

// stage2 vertical update
__device__ __forceinline__ void s2_upd(float vA[4], float vB[4],
                                       const uint4 u, const uint4 o)
{
    float an[4], bn[4], ao[4], bo[4];
    upk(u.x, an[0], bn[0]); upk(u.y, an[1], bn[1]);
    upk(u.z, an[2], bn[2]); upk(u.w, an[3], bn[3]);
    upk(o.x, ao[0], bo[0]); upk(o.y, ao[1], bo[1]);
    upk(o.z, ao[2], bo[2]); upk(o.w, ao[3], bo[3]);
#pragma unroll
    for (int e = 0; e < 4; ++e) {
        vA[e] = __fsub_rn(__fadd_rn(vA[e], an[e]), ao[e]);
        vB[e] = __fsub_rn(__fadd_rn(vB[e], bn[e]), bo[e]);
    }
}

__device__ __forceinline__ void s2_epi(const float wA[4], const float wB[4],
                                       int gi, int col0, bool strip0, int lane,
                                       const float4* __restrict__ Isrc,
                                       float4* __restrict__ dst)
{
    const float inv400 = 1.0f / 400.0f;
    const bool divpath = (gi + 1 < R) || (strip0 && lane < 10);
    const float4 Iv = __ldcs(Isrc);
    const float iv_[4] = {Iv.x, Iv.y, Iv.z, Iv.w};
    float q_[4];
    if (divpath) {
        const float Nrf = (gi + 1 < R) ? (float)(gi + 1) : 20.0f;
#pragma unroll
        for (int e = 0; e < 4; ++e) {
            const int colp1 = col0 + e + 1;
            const float Ncf = (colp1 < R) ? (float)colp1 : 20.0f;
            const float Nf = __fmul_rn(Nrf, Ncf);
            const float mA = __fdiv_rn(wA[e], Nf);
            const float mB = __fdiv_rn(wB[e], Nf);
            q_[e] = __fadd_rn(__fmul_rn(mA, iv_[e]), mB);
        }
    } else {
#pragma unroll
        for (int e = 0; e < 4; ++e) {
            const float mA = wA[e] * inv400;
            const float mB = wB[e] * inv400;
            q_[e] = fmaf(mA, iv_[e], mB);
        }
    }
    __stcs(dst, make_float4(q_[0], q_[1], q_[2], q_[3]));
}

__global__ void __launch_bounds__(TPB, 2)
gf_stage2(const float* __restrict__ gI, float* __restrict__ gQ)
{
    const int lane = threadIdx.x & 31;
    const int j    = threadIdx.x >> 5;
    const int band = blockIdx.x;
    const int img  = blockIdx.y;

    const int mi   = 27 * j - 5 + lane;
    const bool inc = (mi >= 0) && (mi < 256);
    const bool isOut = (lane >= 5) && (mi < 256);
    const int col0 = mi * 4;
    const bool strip0 = (j == 0);

    const int r0 = band * BANDH;
    const int r1 = r0 + BANDH;
    const int gstart = (r0 >= R - 1) ? (r0 - (R - 1)) : 0;
    const int subStart = gstart + R;

    const float4* I4 = (const float4*)(gI + (size_t)img * Hn * Wn);
    const uint4* ABu = g_ABh + (size_t)img * Hn * (Wn / 4);
    float4* Q4 = (float4*)(gQ + (size_t)img * Hn * Wn);

    float vA[4] = {0,0,0,0}, vB[4] = {0,0,0,0};
    const uint4 zu4 = make_uint4(0u,0u,0u,0u);

    // warm-up (bands >= 1): pure accumulation
    for (int gi = gstart; gi < r0; ++gi) {
        uint4 u = zu4;
        if (inc) u = ABu[(gi << 8) + mi];
        s2_upd(vA, vB, u, zu4);
    }

    // main loop: row pairs
    for (int gi = r0; gi < r1; gi += 2) {
        const int g0 = gi, g1 = gi + 1;
        uint4 u0 = zu4, o0 = zu4, u1 = zu4, o1 = zu4;
        if (inc) {
            u0 = ABu[(g0 << 8) + mi];
            u1 = ABu[(g1 << 8) + mi];
            if (g0 >= subStart) o0 = __ldcs(ABu + ((g0 - R) << 8) + mi);
            if (g1 >= subStart) o1 = __ldcs(ABu + ((g1 - R) << 8) + mi);
        }

        s2_upd(vA, vB, u0, o0);
        float wA0[4], wB0[4];
        hwin(vA, wA0); hwin(vB, wB0);

        s2_upd(vA, vB, u1, o1);
        float wA1[4], wB1[4];
        hwin(vA, wA1); hwin(vB, wB1);

        if (isOut) {
            s2_epi(wA0, wB0, g0, col0, strip0, lane, I4 + (g0 << 8) + mi, Q4 + (g0 << 8) + mi);
            s2_epi(wA1, wB1, g1, col0, strip0, lane, I4 + (g1 << 8) + mi, Q4 + (g1 << 8) + mi);
        }
    }
}

extern "C" void kernel_launch(void* const* d_in, const int* in_sizes, int n_in,
                              void* d_out, int out_size)
{
    (void)in_sizes; (void)n_in; (void)out_size;
    const float* I = (const float*)d_in[0];
    const float* p = (const float*)d_in[1];
    float* q = (float*)d_out;

    dim3 grid(NBAND, NIMG);     // 10 warps per CTA cover all 1024 cols
    gf_stage1<<<grid, TPB>>>(I, p);
    gf_stage2<<<grid, TPB>>>(I, q);
}